// round 12
// baseline (speedup 1.0000x reference)
#include <cuda_runtime.h>

#define NTOT 16384   // B*N
#define NPTS 8192    // N per batch
#define KNN  16
#define DOUT 128
#define NLISTS 8     // partial lists per query (2 block-halves x 4 in-block)
#define STKN 12      // per-lane candidate stack depth
#define FLUSH_AT 8   // flush when cnt >= 8 (checked every 2 pairs -> max 11 < 12)
#define TOPK_SMEM (32768 + 32768 + 49152)   // skA + skB + stack = 112KB

// ---- scratch (__device__ globals: allocation-free) ----
__device__ float4 g_keysA[NTOT / 2];     // (x0,x1,y0,y1) per key pair
__device__ float4 g_keysB[NTOT / 2];     // (z0,z1,n0,n1) per key pair
__device__ float  g_Q[NTOT * DOUT];
__device__ float  g_P[NTOT * DOUT];
// partial lists, layout [j*NLISTS + l][q] for coalesced merge; +1 row pad
__device__ float  g_pd[(KNN + 1) * NLISTS * NTOT];
__device__ int    g_pi[(KNN + 1) * NLISTS * NTOT];
__device__ int    g_id[NTOT * KNN];
__device__ float  g_w[NTOT * KNN];

// ---- f32x2 packed helpers (two independent IEEE-rn fp32 ops) ----
__device__ __forceinline__ unsigned long long pk2(float lo, float hi) {
    unsigned long long v;
    asm("mov.b64 %0, {%1, %2};" : "=l"(v) : "f"(lo), "f"(hi));
    return v;
}
__device__ __forceinline__ void unpk2(float& lo, float& hi, unsigned long long v) {
    asm("mov.b64 {%0, %1}, %2;" : "=f"(lo), "=f"(hi) : "l"(v));
}
__device__ __forceinline__ unsigned long long mul2(unsigned long long a, unsigned long long b) {
    unsigned long long d;
    asm("mul.rn.f32x2 %0, %1, %2;" : "=l"(d) : "l"(a), "l"(b));
    return d;
}
__device__ __forceinline__ unsigned long long add2(unsigned long long a, unsigned long long b) {
    unsigned long long d;
    asm("add.rn.f32x2 %0, %1, %2;" : "=l"(d) : "l"(a), "l"(b));
    return d;
}
__device__ __forceinline__ unsigned long long fma2_(unsigned long long a, unsigned long long b,
                                                    unsigned long long c) {
    unsigned long long d;
    asm("fma.rn.f32x2 %0, %1, %2, %3;" : "=l"(d) : "l"(a), "l"(b), "l"(c));
    return d;
}

// packed distance for one key pair: d2 = (qn+kn) - 2*dot, reference rounding
__device__ __forceinline__ void dist2(float4 A, float4 Bv,
                                      unsigned long long qx2, unsigned long long qy2,
                                      unsigned long long qz2, unsigned long long qn2,
                                      unsigned long long m22, float& s0, float& s1) {
    unsigned long long kx2 = *(const unsigned long long*)&A.x;
    unsigned long long ky2 = *(const unsigned long long*)&A.z;
    unsigned long long kz2 = *(const unsigned long long*)&Bv.x;
    unsigned long long kn2 = *(const unsigned long long*)&Bv.z;
    unsigned long long dt = add2(add2(mul2(qx2, kx2), mul2(qy2, ky2)), mul2(qz2, kz2));
    unsigned long long d2 = fma2_(dt, m22, add2(qn2, kn2));   // -2*dot exact
    unpk2(s0, s1, d2);
}

// carry-insert one (d,id) into sorted ascending 16-list, strict <
__device__ __forceinline__ void ins16(float (&d)[KNN], int (&id)[KNN], float cv, int ci) {
#pragma unroll
    for (int t = 0; t < KNN; t++) {
        bool p = cv < d[t];
        float od = d[t]; int oi = id[t];
        d[t]  = p ? cv : od;
        id[t] = p ? ci : oi;
        cv    = p ? od : cv;
        ci    = p ? oi : ci;
    }
}

// ============================================================
// 1) pack keys in pairs: A=(x0,x1,y0,y1), B=(z0,z1,n0,n1)
// ============================================================
__global__ void pack_kernel(const float* __restrict__ xyz1) {
    int p = blockIdx.x * 256 + threadIdx.x;
    if (p >= NTOT / 2) return;
    int k0 = 2 * p;
    float x0 = xyz1[3 * k0 + 0], y0 = xyz1[3 * k0 + 1], z0 = xyz1[3 * k0 + 2];
    float x1 = xyz1[3 * k0 + 3], y1 = xyz1[3 * k0 + 4], z1 = xyz1[3 * k0 + 5];
    float n0 = __fadd_rn(__fadd_rn(__fmul_rn(x0, x0), __fmul_rn(y0, y0)), __fmul_rn(z0, z0));
    float n1 = __fadd_rn(__fadd_rn(__fmul_rn(x1, x1), __fmul_rn(y1, y1)), __fmul_rn(z1, z1));
    g_keysA[p] = make_float4(x0, x1, y0, y1);
    g_keysB[p] = make_float4(z0, z1, n0, n1);
}

// ============================================================
// 2) top-16 NN: 256 blocks x 512 threads.
//    Block (qg, half): 128 queries, 4096 keys, 4-way in-block
//    split -> 1024 keys/lane. BRANCHLESS candidate push:
//    unconditional STS.64 to the free stack slot + predicated
//    cnt advance (no BSSY/BSYNC in the hot loop). 12-deep smem
//    stack, warp-uniform flush@8 checked every 2 pairs.
// ============================================================
__global__ void __launch_bounds__(512, 2) topk_kernel(const float* __restrict__ xyz2) {
    extern __shared__ char smraw[];
    float4* skA = (float4*)smraw;                // 2048 pairs, 32KB
    float4* skB = (float4*)(smraw + 32768);      // 32KB
    float2* stk = (float2*)(smraw + 65536);      // [12][512] 48KB

    int tid  = threadIdx.x;
    int ql   = tid & 127;
    int h    = tid >> 7;
    int qg   = blockIdx.x >> 1;
    int half = blockIdx.x & 1;
    int q    = qg * 128 + ql;
    int b    = q >> 13;

    const float4* gA = g_keysA + b * 4096 + half * 2048;
    const float4* gB = g_keysB + b * 4096 + half * 2048;
    for (int i = tid; i < 2048; i += 512) { skA[i] = gA[i]; skB[i] = gB[i]; }
    __syncthreads();

    float qx = xyz2[3 * q + 0], qy = xyz2[3 * q + 1], qz = xyz2[3 * q + 2];
    float qn = __fadd_rn(__fadd_rn(__fmul_rn(qx, qx), __fmul_rn(qy, qy)), __fmul_rn(qz, qz));
    unsigned long long qx2 = pk2(qx, qx), qy2 = pk2(qy, qy), qz2 = pk2(qz, qz);
    unsigned long long qn2 = pk2(qn, qn), m22 = pk2(-2.0f, -2.0f);
    const float FINF = __int_as_float(0x7f800000);

    float d[KNN];  int id[KNN];
#pragma unroll
    for (int j = 0; j < KNN; j++) { d[j] = 3.0e38f; id[j] = 0; }

    int cnt = 0;
    int pb = h * 512;
    int kb = half * 4096 + h * 1024;     // batch-local key id base

    for (int pp = 0; pp < 512; pp += 2) {
        if (__any_sync(0xffffffffu, cnt >= FLUSH_AT)) {
            for (int j = 0; j < STKN; j++) {
                if (!__any_sync(0xffffffffu, j < cnt)) break;
                float2 e = stk[j * 512 + tid];
                float cv = (j < cnt) ? e.x : FINF;
                ins16(d, id, cv, __float_as_int(e.y));
            }
            cnt = 0;
        }
#pragma unroll
        for (int u = 0; u < 2; u++) {
            float s0, s1;
            dist2(skA[pb + pp + u], skB[pb + pp + u], qx2, qy2, qz2, qn2, m22, s0, s1);
            int k = kb + 2 * (pp + u);
            // branchless push: slot cnt is always free; overwrite is harmless
            stk[min(cnt, STKN - 1) * 512 + tid] = make_float2(s0, __int_as_float(k));
            cnt += (s0 < d[KNN - 1]) ? 1 : 0;
            stk[min(cnt, STKN - 1) * 512 + tid] = make_float2(s1, __int_as_float(k + 1));
            cnt += (s1 < d[KNN - 1]) ? 1 : 0;
        }
    }
    // final flush
    for (int j = 0; j < STKN; j++) {
        if (!__any_sync(0xffffffffu, j < cnt)) break;
        float2 e = stk[j * 512 + tid];
        float cv = (j < cnt) ? e.x : FINF;
        ins16(d, id, cv, __float_as_int(e.y));
    }

    // write sorted partial list, coalesced layout [j*NLISTS + l][q]
    int l = half * 4 + h;
#pragma unroll
    for (int j = 0; j < KNN; j++) {
        g_pd[(size_t)(j * NLISTS + l) * NTOT + q] = d[j];
        g_pi[(size_t)(j * NLISTS + l) * NTOT + q] = id[j];
    }
}

// ============================================================
// 2b) merge 8 sorted 16-lists per query (register heads,
//     coalesced loads), compute inverse-distance weights.
//     Exact top_k tie order: (d, id) lexicographic.
// ============================================================
__global__ void __launch_bounds__(256) merge8_kernel() {
    int q = blockIdx.x * 256 + threadIdx.x;
    float hv[NLISTS]; int hi[NLISTS]; int pos[NLISTS];
#pragma unroll
    for (int l = 0; l < NLISTS; l++) {
        hv[l] = g_pd[(size_t)l * NTOT + q];      // j=0 row
        hi[l] = g_pi[(size_t)l * NTOT + q];
        pos[l] = 0;
    }
    float rd[KNN];
#pragma unroll
    for (int j = 0; j < KNN; j++) {
        float bv = hv[0]; int bi = hi[0]; int bl = 0;
#pragma unroll
        for (int l = 1; l < NLISTS; l++) {
            bool t = (hv[l] < bv) || (hv[l] == bv && hi[l] < bi);
            bv = t ? hv[l] : bv;
            bi = t ? hi[l] : bi;
            bl = t ? l : bl;
        }
        rd[j] = bv;
        g_id[q * KNN + j] = bi;
#pragma unroll
        for (int l = 0; l < NLISTS; l++) {
            bool adv = (l == bl);
            int np = pos[l] + (adv ? 1 : 0);
            pos[l] = np;
            if (adv) {
                size_t o = (size_t)(np * NLISTS + l) * NTOT + q;   // pad row safe
                hv[l] = g_pd[o]; hi[l] = g_pi[o];
            }
        }
    }
    float r[KNN]; float sum = 0.f;
#pragma unroll
    for (int j = 0; j < KNN; j++) {
        r[j] = __fdiv_rn(1.0f, __fadd_rn(rd[j], 1e-8f));
        sum = __fadd_rn(sum, r[j]);
    }
#pragma unroll
    for (int j = 0; j < KNN; j++)
        g_w[q * KNN + j] = __fdiv_rn(r[j], sum);
}

// ============================================================
// 3) SGEMM: C[m,o]=sum_c A[m,c]*W[o,wcol0+c](+bias)
// ============================================================
__global__ void __launch_bounds__(256) gemm_kernel(
        const float* __restrict__ A, int K,
        const float* __restrict__ W, int wcol0,
        const float* __restrict__ bias, int dst)
{
    __shared__ float As[16][132];
    __shared__ float Bs[16][132];
    float* C = dst ? g_P : g_Q;

    int tid = threadIdx.x;
    int m0 = blockIdx.x * 128;
    int tx = tid & 15;
    int ty = tid >> 4;
    int lr = tid >> 2;
    int lc = (tid & 3) << 2;

    float acc[8][8];
#pragma unroll
    for (int i = 0; i < 8; i++)
#pragma unroll
        for (int j = 0; j < 8; j++) acc[i][j] = 0.f;

    for (int kt = 0; kt < K; kt += 16) {
        float4 a0 = *(const float4*)(A + (size_t)(m0 + lr) * K + kt + lc);
        float4 a1 = *(const float4*)(A + (size_t)(m0 + lr + 64) * K + kt + lc);
        float4 b0 = *(const float4*)(W + (size_t)lr * 384 + wcol0 + kt + lc);
        float4 b1 = *(const float4*)(W + (size_t)(lr + 64) * 384 + wcol0 + kt + lc);
        __syncthreads();
        As[lc + 0][lr] = a0.x; As[lc + 1][lr] = a0.y; As[lc + 2][lr] = a0.z; As[lc + 3][lr] = a0.w;
        As[lc + 0][lr + 64] = a1.x; As[lc + 1][lr + 64] = a1.y; As[lc + 2][lr + 64] = a1.z; As[lc + 3][lr + 64] = a1.w;
        Bs[lc + 0][lr] = b0.x; Bs[lc + 1][lr] = b0.y; Bs[lc + 2][lr] = b0.z; Bs[lc + 3][lr] = b0.w;
        Bs[lc + 0][lr + 64] = b1.x; Bs[lc + 1][lr + 64] = b1.y; Bs[lc + 2][lr + 64] = b1.z; Bs[lc + 3][lr + 64] = b1.w;
        __syncthreads();
#pragma unroll
        for (int kk = 0; kk < 16; kk++) {
            float4 af0 = *(float4*)&As[kk][ty * 4];
            float4 af1 = *(float4*)&As[kk][ty * 4 + 64];
            float4 bf0 = *(float4*)&Bs[kk][tx * 4];
            float4 bf1 = *(float4*)&Bs[kk][tx * 4 + 64];
            float av[8] = {af0.x, af0.y, af0.z, af0.w, af1.x, af1.y, af1.z, af1.w};
            float bv[8] = {bf0.x, bf0.y, bf0.z, bf0.w, bf1.x, bf1.y, bf1.z, bf1.w};
#pragma unroll
            for (int i = 0; i < 8; i++)
#pragma unroll
                for (int j = 0; j < 8; j++)
                    acc[i][j] = fmaf(av[i], bv[j], acc[i][j]);
        }
    }

    float bb[8] = {0.f, 0.f, 0.f, 0.f, 0.f, 0.f, 0.f, 0.f};
    if (bias) {
        float4 x0 = *(const float4*)(bias + tx * 4);
        float4 x1 = *(const float4*)(bias + tx * 4 + 64);
        bb[0] = x0.x; bb[1] = x0.y; bb[2] = x0.z; bb[3] = x0.w;
        bb[4] = x1.x; bb[5] = x1.y; bb[6] = x1.z; bb[7] = x1.w;
    }
#pragma unroll
    for (int i = 0; i < 8; i++) {
        int row = m0 + ty * 4 + (i < 4 ? i : 64 + i - 4);
        float4 v0 = make_float4(acc[i][0] + bb[0], acc[i][1] + bb[1],
                                acc[i][2] + bb[2], acc[i][3] + bb[3]);
        float4 v1 = make_float4(acc[i][4] + bb[4], acc[i][5] + bb[5],
                                acc[i][6] + bb[6], acc[i][7] + bb[7]);
        *(float4*)(C + (size_t)row * DOUT + tx * 4) = v0;
        *(float4*)(C + (size_t)row * DOUT + tx * 4 + 64) = v1;
    }
}

// ============================================================
// 4) combine (float4): warp per query, 4 queries per block
// ============================================================
__global__ void __launch_bounds__(128) combine_kernel(float* __restrict__ out) {
    int w = threadIdx.x >> 5, lane = threadIdx.x & 31;
    int q = blockIdx.x * 4 + w;
    __shared__ float sw[4][KNN];
    __shared__ int   sid[4][KNN];
    if (threadIdx.x < 64) {
        int wq = threadIdx.x >> 4, j = threadIdx.x & 15;
        sw[wq][j]  = g_w[(blockIdx.x * 4 + wq) * KNN + j];
        sid[wq][j] = g_id[(blockIdx.x * 4 + wq) * KNN + j];
    }
    __syncthreads();
    int base = q & ~(NPTS - 1);
    float4 acc = ((const float4*)(g_Q + (size_t)q * DOUT))[lane];
#pragma unroll
    for (int j = 0; j < KNN; j++) {
        float4 p = ((const float4*)(g_P + (size_t)(base + sid[w][j]) * DOUT))[lane];
        float wg = sw[w][j];
        acc.x = fmaf(wg, p.x, acc.x);
        acc.y = fmaf(wg, p.y, acc.y);
        acc.z = fmaf(wg, p.z, acc.z);
        acc.w = fmaf(wg, p.w, acc.w);
    }
    ((float4*)(out + (size_t)q * DOUT))[lane] = acc;
}

// ============================================================
// launcher: fork-join; both GEMMs on concurrent side streams
// ============================================================
static cudaStream_t s_g1 = nullptr, s_g2 = nullptr;
static cudaEvent_t  s_evFork = nullptr, s_evJ1 = nullptr, s_evJ2 = nullptr;

extern "C" void kernel_launch(void* const* d_in, const int* in_sizes, int n_in,
                              void* d_out, int out_size) {
    const float* xyz1    = (const float*)d_in[0];
    const float* xyz2    = (const float*)d_in[1];
    const float* points1 = (const float*)d_in[2];
    const float* points2 = (const float*)d_in[3];
    const float* W       = (const float*)d_in[4];
    const float* bias    = (const float*)d_in[5];
    (void)in_sizes; (void)n_in; (void)out_size;

    if (s_g1 == nullptr) {
        cudaStreamCreateWithFlags(&s_g1, cudaStreamNonBlocking);
        cudaStreamCreateWithFlags(&s_g2, cudaStreamNonBlocking);
        cudaEventCreateWithFlags(&s_evFork, cudaEventDisableTiming);
        cudaEventCreateWithFlags(&s_evJ1, cudaEventDisableTiming);
        cudaEventCreateWithFlags(&s_evJ2, cudaEventDisableTiming);
        cudaFuncSetAttribute(topk_kernel,
                             cudaFuncAttributeMaxDynamicSharedMemorySize, TOPK_SMEM);
    }

    cudaEventRecord(s_evFork, 0);
    cudaStreamWaitEvent(s_g1, s_evFork, 0);
    cudaStreamWaitEvent(s_g2, s_evFork, 0);

    // concurrent GEMMs (independent of kNN pipeline)
    gemm_kernel<<<NTOT / 128, 256, 0, s_g1>>>(points1, 128, W, 0,   bias,    0); // g_Q
    gemm_kernel<<<NTOT / 128, 256, 0, s_g2>>>(points2, 256, W, 128, nullptr, 1); // g_P
    cudaEventRecord(s_evJ1, s_g1);
    cudaEventRecord(s_evJ2, s_g2);

    // main stream: kNN pipeline
    pack_kernel<<<(NTOT / 2 + 255) / 256, 256>>>(xyz1);
    topk_kernel<<<256, 512, TOPK_SMEM>>>(xyz2);
    merge8_kernel<<<NTOT / 256, 256>>>();

    cudaStreamWaitEvent(0, s_evJ1, 0);
    cudaStreamWaitEvent(0, s_evJ2, 0);
    combine_kernel<<<NTOT / 4, 128>>>((float*)d_out);
}

// round 14
// speedup vs baseline: 1.1549x; 1.1549x over previous
#include <cuda_runtime.h>

#define NTOT 16384   // B*N
#define NPTS 8192    // N per batch
#define KNN  16
#define DOUT 128
#define NLISTS 8     // partial lists per query (2 block-halves x 4 in-block)
#define STKN 12      // per-lane candidate stack depth
#define FLUSH_AT 8   // flush when cnt >= 8 (checked every 2 pairs -> max 11 < 12)
#define TOPK_SMEM (32768 + 32768 + 49152)   // skA + skB + stack = 112KB

// ---- scratch (__device__ globals: allocation-free) ----
__device__ float4 g_keysA[NTOT / 2];     // (x0,x1,y0,y1) per key pair
__device__ float4 g_keysB[NTOT / 2];     // (z0,z1,n0,n1) per key pair
__device__ float  g_Q[NTOT * DOUT];
__device__ float  g_P[NTOT * DOUT];
__device__ float  g_T0[NTOT];            // per-query threshold (>= true 16th dist)
// partial lists, layout [j*NLISTS + l][q] for coalesced merge; +1 row pad
__device__ float  g_pd[(KNN + 1) * NLISTS * NTOT];
__device__ int    g_pi[(KNN + 1) * NLISTS * NTOT];
__device__ int    g_id[NTOT * KNN];
__device__ float  g_w[NTOT * KNN];

// ---- f32x2 packed helpers (two independent IEEE-rn fp32 ops) ----
__device__ __forceinline__ unsigned long long pk2(float lo, float hi) {
    unsigned long long v;
    asm("mov.b64 %0, {%1, %2};" : "=l"(v) : "f"(lo), "f"(hi));
    return v;
}
__device__ __forceinline__ void unpk2(float& lo, float& hi, unsigned long long v) {
    asm("mov.b64 {%0, %1}, %2;" : "=f"(lo), "=f"(hi) : "l"(v));
}
__device__ __forceinline__ unsigned long long mul2(unsigned long long a, unsigned long long b) {
    unsigned long long d;
    asm("mul.rn.f32x2 %0, %1, %2;" : "=l"(d) : "l"(a), "l"(b));
    return d;
}
__device__ __forceinline__ unsigned long long add2(unsigned long long a, unsigned long long b) {
    unsigned long long d;
    asm("add.rn.f32x2 %0, %1, %2;" : "=l"(d) : "l"(a), "l"(b));
    return d;
}
__device__ __forceinline__ unsigned long long fma2_(unsigned long long a, unsigned long long b,
                                                    unsigned long long c) {
    unsigned long long d;
    asm("fma.rn.f32x2 %0, %1, %2, %3;" : "=l"(d) : "l"(a), "l"(b), "l"(c));
    return d;
}

// packed distance for one key pair: d2 = (qn+kn) - 2*dot, reference rounding
__device__ __forceinline__ void dist2(float4 A, float4 Bv,
                                      unsigned long long qx2, unsigned long long qy2,
                                      unsigned long long qz2, unsigned long long qn2,
                                      unsigned long long m22, float& s0, float& s1) {
    unsigned long long kx2 = *(const unsigned long long*)&A.x;
    unsigned long long ky2 = *(const unsigned long long*)&A.z;
    unsigned long long kz2 = *(const unsigned long long*)&Bv.x;
    unsigned long long kn2 = *(const unsigned long long*)&Bv.z;
    unsigned long long dt = add2(add2(mul2(qx2, kx2), mul2(qy2, ky2)), mul2(qz2, kz2));
    unsigned long long d2 = fma2_(dt, m22, add2(qn2, kn2));   // -2*dot exact
    unpk2(s0, s1, d2);
}

// carry-insert one (d,id) into sorted ascending 16-list, strict <
__device__ __forceinline__ void ins16(float (&d)[KNN], int (&id)[KNN], float cv, int ci) {
#pragma unroll
    for (int t = 0; t < KNN; t++) {
        bool p = cv < d[t];
        float od = d[t]; int oi = id[t];
        d[t]  = p ? cv : od;
        id[t] = p ? ci : oi;
        cv    = p ? od : cv;
        ci    = p ? oi : ci;
    }
}

// values-only carry-insert (2 ops/slot)
__device__ __forceinline__ void insv16(float (&d)[KNN], float cv) {
#pragma unroll
    for (int t = 0; t < KNN; t++) {
        float lo = fminf(cv, d[t]);
        cv = fmaxf(cv, d[t]);
        d[t] = lo;
    }
}

// ============================================================
// 1) pack keys in pairs: A=(x0,x1,y0,y1), B=(z0,z1,n0,n1)
// ============================================================
__global__ void pack_kernel(const float* __restrict__ xyz1) {
    int p = blockIdx.x * 256 + threadIdx.x;
    if (p >= NTOT / 2) return;
    int k0 = 2 * p;
    float x0 = xyz1[3 * k0 + 0], y0 = xyz1[3 * k0 + 1], z0 = xyz1[3 * k0 + 2];
    float x1 = xyz1[3 * k0 + 3], y1 = xyz1[3 * k0 + 4], z1 = xyz1[3 * k0 + 5];
    float n0 = __fadd_rn(__fadd_rn(__fmul_rn(x0, x0), __fmul_rn(y0, y0)), __fmul_rn(z0, z0));
    float n1 = __fadd_rn(__fadd_rn(__fmul_rn(x1, x1), __fmul_rn(y1, y1)), __fmul_rn(z1, z1));
    g_keysA[p] = make_float4(x0, x1, y0, y1);
    g_keysB[p] = make_float4(z0, z1, n0, n1);
}

// ============================================================
// 1b) sample kernel: T0[q] = exact 16th-smallest distance over a
//     512-key per-query sample (subset => T0 >= true 16th).
//     128 blocks x 512 threads: 128 queries x 4 lanes, 64 pairs
//     per lane (broadcast LDG), values-only top-16, 4-way merge.
// ============================================================
__global__ void __launch_bounds__(512) sample_kernel(const float* __restrict__ xyz2) {
    __shared__ float sv[4 * 128 * KNN];   // 32KB
    int tid = threadIdx.x;
    int ql  = tid & 127;
    int h   = tid >> 7;
    int q   = blockIdx.x * 128 + ql;
    int b   = q >> 13;
    const float4* gA = g_keysA + b * 4096;
    const float4* gB = g_keysB + b * 4096;

    float qx = xyz2[3 * q + 0], qy = xyz2[3 * q + 1], qz = xyz2[3 * q + 2];
    float qn = __fadd_rn(__fadd_rn(__fmul_rn(qx, qx), __fmul_rn(qy, qy)), __fmul_rn(qz, qz));
    unsigned long long qx2 = pk2(qx, qx), qy2 = pk2(qy, qy), qz2 = pk2(qz, qz);
    unsigned long long qn2 = pk2(qn, qn), m22 = pk2(-2.0f, -2.0f);

    float d[KNN];
#pragma unroll
    for (int j = 0; j < KNN; j++) d[j] = 3.0e38f;

#pragma unroll 4
    for (int i = 0; i < 64; i++) {
        int p = h * 1024 + i * 16;          // 64 pairs/lane, stride 16
        float s0, s1;
        dist2(gA[p], gB[p], qx2, qy2, qz2, qn2, m22, s0, s1);
        if (s0 < d[KNN - 1]) insv16(d, s0);
        if (s1 < d[KNN - 1]) insv16(d, s1);
    }
#pragma unroll
    for (int j = 0; j < KNN; j++) sv[(h * 128 + ql) * KNN + j] = d[j];
    __syncthreads();

    if (h == 0) {
        const float FINF = __int_as_float(0x7f800000);
        int pos[4] = {0, 0, 0, 0};
        float heads[4];
#pragma unroll
        for (int l = 0; l < 4; l++) heads[l] = sv[(l * 128 + ql) * KNN];
        float T = 0.f;
#pragma unroll
        for (int j = 0; j < KNN; j++) {
            int bl = 0; float bv = heads[0];
#pragma unroll
            for (int l = 1; l < 4; l++) {
                bool t = heads[l] < bv;
                bv = t ? heads[l] : bv;
                bl = t ? l : bl;
            }
            T = bv;
            int np = pos[bl] + 1;
            pos[bl] = np;
            heads[bl] = (np < KNN) ? sv[(bl * 128 + ql) * KNN + np] : FINF;
        }
        g_T0[q] = T;    // 16th of 512-key sample >= true global 16th
    }
}

// ============================================================
// 2) top-16 NN: 256 blocks x 512 threads.
//    Push filter s <= T0[q] (constant compare, no dependency on
//    the top-16 list). Hits/lane ~32 instead of ~70 => half the
//    flush bill. Overflow bound: store index <= 10 < 12 always.
// ============================================================
__global__ void __launch_bounds__(512, 2) topk_kernel(const float* __restrict__ xyz2) {
    extern __shared__ char smraw[];
    float4* skA = (float4*)smraw;                // 2048 pairs, 32KB
    float4* skB = (float4*)(smraw + 32768);      // 32KB
    float2* stk = (float2*)(smraw + 65536);      // [12][512] 48KB

    int tid  = threadIdx.x;
    int ql   = tid & 127;
    int h    = tid >> 7;
    int qg   = blockIdx.x >> 1;
    int half = blockIdx.x & 1;
    int q    = qg * 128 + ql;
    int b    = q >> 13;

    const float4* gA = g_keysA + b * 4096 + half * 2048;
    const float4* gB = g_keysB + b * 4096 + half * 2048;
    for (int i = tid; i < 2048; i += 512) { skA[i] = gA[i]; skB[i] = gB[i]; }
    __syncthreads();

    float T0 = g_T0[q];
    float qx = xyz2[3 * q + 0], qy = xyz2[3 * q + 1], qz = xyz2[3 * q + 2];
    float qn = __fadd_rn(__fadd_rn(__fmul_rn(qx, qx), __fmul_rn(qy, qy)), __fmul_rn(qz, qz));
    unsigned long long qx2 = pk2(qx, qx), qy2 = pk2(qy, qy), qz2 = pk2(qz, qz);
    unsigned long long qn2 = pk2(qn, qn), m22 = pk2(-2.0f, -2.0f);
    const float FINF = __int_as_float(0x7f800000);

    float d[KNN];  int id[KNN];
#pragma unroll
    for (int j = 0; j < KNN; j++) { d[j] = 3.0e38f; id[j] = 0; }

    int cnt = 0;
    int pb = h * 512;
    int kb = half * 4096 + h * 1024;     // batch-local key id base

    for (int pp = 0; pp < 512; pp += 2) {
        if (__any_sync(0xffffffffu, cnt >= FLUSH_AT)) {
            for (int j = 0; j < STKN; j++) {
                if (!__any_sync(0xffffffffu, j < cnt)) break;
                float2 e = stk[j * 512 + tid];
                float cv = (j < cnt) ? e.x : FINF;
                ins16(d, id, cv, __float_as_int(e.y));
            }
            cnt = 0;
        }
#pragma unroll
        for (int u = 0; u < 2; u++) {
            float s0, s1;
            dist2(skA[pb + pp + u], skB[pb + pp + u], qx2, qy2, qz2, qn2, m22, s0, s1);
            int k = kb + 2 * (pp + u);
            // branchless push; slot cnt always free (store index <= 10)
            stk[cnt * 512 + tid] = make_float2(s0, __int_as_float(k));
            cnt += (s0 <= T0) ? 1 : 0;
            stk[cnt * 512 + tid] = make_float2(s1, __int_as_float(k + 1));
            cnt += (s1 <= T0) ? 1 : 0;
        }
    }
    // final flush
    for (int j = 0; j < STKN; j++) {
        if (!__any_sync(0xffffffffu, j < cnt)) break;
        float2 e = stk[j * 512 + tid];
        float cv = (j < cnt) ? e.x : FINF;
        ins16(d, id, cv, __float_as_int(e.y));
    }

    // write sorted partial list, coalesced layout [j*NLISTS + l][q]
    int l = half * 4 + h;
#pragma unroll
    for (int j = 0; j < KNN; j++) {
        g_pd[(size_t)(j * NLISTS + l) * NTOT + q] = d[j];
        g_pi[(size_t)(j * NLISTS + l) * NTOT + q] = id[j];
    }
}

// ============================================================
// 2b) merge 8 sorted 16-lists per query (register heads,
//     coalesced loads), compute inverse-distance weights.
//     Exact top_k tie order: (d, id) lexicographic.
// ============================================================
__global__ void __launch_bounds__(256) merge8_kernel() {
    int q = blockIdx.x * 256 + threadIdx.x;
    float hv[NLISTS]; int hi[NLISTS]; int pos[NLISTS];
#pragma unroll
    for (int l = 0; l < NLISTS; l++) {
        hv[l] = g_pd[(size_t)l * NTOT + q];      // j=0 row
        hi[l] = g_pi[(size_t)l * NTOT + q];
        pos[l] = 0;
    }
    float rd[KNN];
#pragma unroll
    for (int j = 0; j < KNN; j++) {
        float bv = hv[0]; int bi = hi[0]; int bl = 0;
#pragma unroll
        for (int l = 1; l < NLISTS; l++) {
            bool t = (hv[l] < bv) || (hv[l] == bv && hi[l] < bi);
            bv = t ? hv[l] : bv;
            bi = t ? hi[l] : bi;
            bl = t ? l : bl;
        }
        rd[j] = bv;
        g_id[q * KNN + j] = bi;
#pragma unroll
        for (int l = 0; l < NLISTS; l++) {
            bool adv = (l == bl);
            int np = pos[l] + (adv ? 1 : 0);
            pos[l] = np;
            if (adv) {
                size_t o = (size_t)(np * NLISTS + l) * NTOT + q;   // pad row safe
                hv[l] = g_pd[o]; hi[l] = g_pi[o];
            }
        }
    }
    float r[KNN]; float sum = 0.f;
#pragma unroll
    for (int j = 0; j < KNN; j++) {
        r[j] = __fdiv_rn(1.0f, __fadd_rn(rd[j], 1e-8f));
        sum = __fadd_rn(sum, r[j]);
    }
#pragma unroll
    for (int j = 0; j < KNN; j++)
        g_w[q * KNN + j] = __fdiv_rn(r[j], sum);
}

// ============================================================
// 3) SGEMM: C[m,o]=sum_c A[m,c]*W[o,wcol0+c](+bias)
// ============================================================
__global__ void __launch_bounds__(256) gemm_kernel(
        const float* __restrict__ A, int K,
        const float* __restrict__ W, int wcol0,
        const float* __restrict__ bias, int dst)
{
    __shared__ float As[16][132];
    __shared__ float Bs[16][132];
    float* C = dst ? g_P : g_Q;

    int tid = threadIdx.x;
    int m0 = blockIdx.x * 128;
    int tx = tid & 15;
    int ty = tid >> 4;
    int lr = tid >> 2;
    int lc = (tid & 3) << 2;

    float acc[8][8];
#pragma unroll
    for (int i = 0; i < 8; i++)
#pragma unroll
        for (int j = 0; j < 8; j++) acc[i][j] = 0.f;

    for (int kt = 0; kt < K; kt += 16) {
        float4 a0 = *(const float4*)(A + (size_t)(m0 + lr) * K + kt + lc);
        float4 a1 = *(const float4*)(A + (size_t)(m0 + lr + 64) * K + kt + lc);
        float4 b0 = *(const float4*)(W + (size_t)lr * 384 + wcol0 + kt + lc);
        float4 b1 = *(const float4*)(W + (size_t)(lr + 64) * 384 + wcol0 + kt + lc);
        __syncthreads();
        As[lc + 0][lr] = a0.x; As[lc + 1][lr] = a0.y; As[lc + 2][lr] = a0.z; As[lc + 3][lr] = a0.w;
        As[lc + 0][lr + 64] = a1.x; As[lc + 1][lr + 64] = a1.y; As[lc + 2][lr + 64] = a1.z; As[lc + 3][lr + 64] = a1.w;
        Bs[lc + 0][lr] = b0.x; Bs[lc + 1][lr] = b0.y; Bs[lc + 2][lr] = b0.z; Bs[lc + 3][lr] = b0.w;
        Bs[lc + 0][lr + 64] = b1.x; Bs[lc + 1][lr + 64] = b1.y; Bs[lc + 2][lr + 64] = b1.z; Bs[lc + 3][lr + 64] = b1.w;
        __syncthreads();
#pragma unroll
        for (int kk = 0; kk < 16; kk++) {
            float4 af0 = *(float4*)&As[kk][ty * 4];
            float4 af1 = *(float4*)&As[kk][ty * 4 + 64];
            float4 bf0 = *(float4*)&Bs[kk][tx * 4];
            float4 bf1 = *(float4*)&Bs[kk][tx * 4 + 64];
            float av[8] = {af0.x, af0.y, af0.z, af0.w, af1.x, af1.y, af1.z, af1.w};
            float bv[8] = {bf0.x, bf0.y, bf0.z, bf0.w, bf1.x, bf1.y, bf1.z, bf1.w};
#pragma unroll
            for (int i = 0; i < 8; i++)
#pragma unroll
                for (int j = 0; j < 8; j++)
                    acc[i][j] = fmaf(av[i], bv[j], acc[i][j]);
        }
    }

    float bb[8] = {0.f, 0.f, 0.f, 0.f, 0.f, 0.f, 0.f, 0.f};
    if (bias) {
        float4 x0 = *(const float4*)(bias + tx * 4);
        float4 x1 = *(const float4*)(bias + tx * 4 + 64);
        bb[0] = x0.x; bb[1] = x0.y; bb[2] = x0.z; bb[3] = x0.w;
        bb[4] = x1.x; bb[5] = x1.y; bb[6] = x1.z; bb[7] = x1.w;
    }
#pragma unroll
    for (int i = 0; i < 8; i++) {
        int row = m0 + ty * 4 + (i < 4 ? i : 64 + i - 4);
        float4 v0 = make_float4(acc[i][0] + bb[0], acc[i][1] + bb[1],
                                acc[i][2] + bb[2], acc[i][3] + bb[3]);
        float4 v1 = make_float4(acc[i][4] + bb[4], acc[i][5] + bb[5],
                                acc[i][6] + bb[6], acc[i][7] + bb[7]);
        *(float4*)(C + (size_t)row * DOUT + tx * 4) = v0;
        *(float4*)(C + (size_t)row * DOUT + tx * 4 + 64) = v1;
    }
}

// ============================================================
// 4) combine (float4): warp per query, 4 queries per block
// ============================================================
__global__ void __launch_bounds__(128) combine_kernel(float* __restrict__ out) {
    int w = threadIdx.x >> 5, lane = threadIdx.x & 31;
    int q = blockIdx.x * 4 + w;
    __shared__ float sw[4][KNN];
    __shared__ int   sid[4][KNN];
    if (threadIdx.x < 64) {
        int wq = threadIdx.x >> 4, j = threadIdx.x & 15;
        sw[wq][j]  = g_w[(blockIdx.x * 4 + wq) * KNN + j];
        sid[wq][j] = g_id[(blockIdx.x * 4 + wq) * KNN + j];
    }
    __syncthreads();
    int base = q & ~(NPTS - 1);
    float4 acc = ((const float4*)(g_Q + (size_t)q * DOUT))[lane];
#pragma unroll
    for (int j = 0; j < KNN; j++) {
        float4 p = ((const float4*)(g_P + (size_t)(base + sid[w][j]) * DOUT))[lane];
        float wg = sw[w][j];
        acc.x = fmaf(wg, p.x, acc.x);
        acc.y = fmaf(wg, p.y, acc.y);
        acc.z = fmaf(wg, p.z, acc.z);
        acc.w = fmaf(wg, p.w, acc.w);
    }
    ((float4*)(out + (size_t)q * DOUT))[lane] = acc;
}

// ============================================================
// launcher: fork-join; both GEMMs on concurrent side streams
// ============================================================
static cudaStream_t s_g1 = nullptr, s_g2 = nullptr;
static cudaEvent_t  s_evFork = nullptr, s_evJ1 = nullptr, s_evJ2 = nullptr;

extern "C" void kernel_launch(void* const* d_in, const int* in_sizes, int n_in,
                              void* d_out, int out_size) {
    const float* xyz1    = (const float*)d_in[0];
    const float* xyz2    = (const float*)d_in[1];
    const float* points1 = (const float*)d_in[2];
    const float* points2 = (const float*)d_in[3];
    const float* W       = (const float*)d_in[4];
    const float* bias    = (const float*)d_in[5];
    (void)in_sizes; (void)n_in; (void)out_size;

    if (s_g1 == nullptr) {
        cudaStreamCreateWithFlags(&s_g1, cudaStreamNonBlocking);
        cudaStreamCreateWithFlags(&s_g2, cudaStreamNonBlocking);
        cudaEventCreateWithFlags(&s_evFork, cudaEventDisableTiming);
        cudaEventCreateWithFlags(&s_evJ1, cudaEventDisableTiming);
        cudaEventCreateWithFlags(&s_evJ2, cudaEventDisableTiming);
        cudaFuncSetAttribute(topk_kernel,
                             cudaFuncAttributeMaxDynamicSharedMemorySize, TOPK_SMEM);
    }

    cudaEventRecord(s_evFork, 0);
    cudaStreamWaitEvent(s_g1, s_evFork, 0);
    cudaStreamWaitEvent(s_g2, s_evFork, 0);

    // concurrent GEMMs (independent of kNN pipeline)
    gemm_kernel<<<NTOT / 128, 256, 0, s_g1>>>(points1, 128, W, 0,   bias,    0); // g_Q
    gemm_kernel<<<NTOT / 128, 256, 0, s_g2>>>(points2, 256, W, 128, nullptr, 1); // g_P
    cudaEventRecord(s_evJ1, s_g1);
    cudaEventRecord(s_evJ2, s_g2);

    // main stream: kNN pipeline
    pack_kernel<<<(NTOT / 2 + 255) / 256, 256>>>(xyz1);
    sample_kernel<<<NTOT / 128, 512>>>(xyz2);
    topk_kernel<<<256, 512, TOPK_SMEM>>>(xyz2);
    merge8_kernel<<<NTOT / 256, 256>>>();

    cudaStreamWaitEvent(0, s_evJ1, 0);
    cudaStreamWaitEvent(0, s_evJ2, 0);
    combine_kernel<<<NTOT / 4, 128>>>((float*)d_out);
}